// round 12
// baseline (speedup 1.0000x reference)
#include <cuda_runtime.h>
#include <cuda_fp16.h>
#include <cstdint>

#define NN 4
#define C  64
#define H  160
#define W  320
#define DISP 48
#define G  8
#define HW (H*W)
#define ROWB 16                        // 8 halfs per w position (one group)
#define SMEM_BYTES (W * ROWB)          // 5KB

// Swizzle for 16B rows: XOR 16B-chunk bits [4:7) with bits [7:10).
// Compute lanes step w by 2: chunk (w&7)^((w>>3)&7) spans two 8-blocks with
// keys K,K^1 -> {even chunks}^K U {odd chunks}^K = all 8 distinct.
// Staging lanes step w by 1: within an 8-block, (w&7)^K all distinct.
__device__ __forceinline__ unsigned sw16(int w) {
    unsigned off = (unsigned)w * 16u;
    off ^= (((unsigned)w >> 3) & 7u) << 4;
    return off;
}

// Load position w (8 fp16 channels, one LDS.128) and convert to 2 float4.
#define LDCVT(wpos, a, b) do {                                  \
    uint4 _hv = *(const uint4*)(rS + sw16(wpos));               \
    float2 _f0 = __half22float2(*(__half2*)&_hv.x);             \
    float2 _f1 = __half22float2(*(__half2*)&_hv.y);             \
    float2 _f2 = __half22float2(*(__half2*)&_hv.z);             \
    float2 _f3 = __half22float2(*(__half2*)&_hv.w);             \
    (a) = make_float4(_f0.x, _f0.y, _f1.x, _f1.y);              \
    (b) = make_float4(_f2.x, _f2.y, _f3.x, _f3.y);              \
} while (0)

// dot, two independent 4-FFMA chains + add (l pre-scaled by 1/8).
#define DOT(lw, s)                                                      \
    ((lw[0]*ra[s].x + lw[1]*ra[s].y + lw[2]*ra[s].z + lw[3]*ra[s].w) +  \
     (lw[4]*rb[s].x + lw[5]*rb[s].y + lw[6]*rb[s].z + lw[7]*rb[s].w))

__global__ __launch_bounds__(160, 6)
void gwc_kernel(const float* __restrict__ lg,
                const float* __restrict__ rg,
                float* __restrict__ out) {
    __shared__ __align__(16) char rS[SMEM_BYTES];

    const int h   = blockIdx.x;
    const int n   = blockIdx.y;
    const int g   = blockIdx.z;
    const int tid = threadIdx.x;
    const int w0  = tid * 2;             // this thread's 2 output columns

    // ---- l loads first: 8 coalesced LDG.64; pre-scale by 1/8 (fp32) ----
    const float* lp = lg + ((n * C + g * 8) * H + h) * W + w0;
    float lwA[8], lwB[8];
    #pragma unroll
    for (int c = 0; c < 8; ++c) {
        float2 v = *(const float2*)(lp + c * HW);
        lwA[c] = v.x * 0.125f; lwB[c] = v.y * 0.125f;
    }

    // ---- Stage r channels as fp16, transposed [w][8ch], swizzled ----
    // 320 positions, 2 per thread: 8 coalesced scalar LDG + 4 F2H2 + STS.128.
    {
        const float* rbase = rg + ((n * C + g * 8) * H + h) * W;
        #pragma unroll
        for (int k = 0; k < 2; ++k) {
            int w = tid + k * 160;
            float f[8];
            #pragma unroll
            for (int c = 0; c < 8; ++c) f[c] = rbase[c * HW + w];
            uint4 hv;
            *(__half2*)&hv.x = __float22half2_rn(make_float2(f[0], f[1]));
            *(__half2*)&hv.y = __float22half2_rn(make_float2(f[2], f[3]));
            *(__half2*)&hv.z = __float22half2_rn(make_float2(f[4], f[5]));
            *(__half2*)&hv.w = __float22half2_rn(make_float2(f[6], f[7]));
            *(uint4*)(rS + sw16(w)) = hv;
        }
    }
    __syncthreads();

    // ---- Compute: 2-slot sliding window over disparity (ring in fp32) ----
    float4 ra[2], rb[2];                 // slot p = parity of r position
    LDCVT(w0,     ra[0], rb[0]);
    LDCVT(w0 + 1, ra[1], rb[1]);

    float* op = out + (((n * G + g) * DISP) * H + h) * W + w0;

    if (w0 >= DISP) {
        #pragma unroll 4
        for (int d2 = 0; d2 < DISP; d2 += 2) {
            // d = d2 (even): output x parity 0, y parity 1
            if (d2 > 0) LDCVT(w0 - d2, ra[0], rb[0]);
            float2 o01;
            o01.x = DOT(lwA, 0);
            o01.y = DOT(lwB, 1);
            __stcs((float2*)op, o01);

            // d = d2+1 (odd): new position w0-d2-1 has parity 1
            LDCVT(w0 - d2 - 1, ra[1], rb[1]);
            o01.x = DOT(lwA, 1);
            o01.y = DOT(lwB, 0);
            __stcs((float2*)(op + HW), o01);

            op += 2 * HW;
        }
    } else {
        #pragma unroll 4
        for (int d2 = 0; d2 < DISP; d2 += 2) {
            const int wn0 = w0 - d2;
            if (d2 > 0 && wn0 >= 0) LDCVT(wn0, ra[0], rb[0]);
            float2 o01;
            o01.x = (w0     >= d2) ? DOT(lwA, 0) : 1.0f;
            o01.y = (w0 + 1 >= d2) ? DOT(lwB, 1) : 1.0f;
            __stcs((float2*)op, o01);

            const int wn1 = w0 - d2 - 1;
            if (wn1 >= 0) LDCVT(wn1, ra[1], rb[1]);
            o01.x = (w0     >= d2 + 1) ? DOT(lwA, 1) : 1.0f;
            o01.y = (w0 + 1 >= d2 + 1) ? DOT(lwB, 0) : 1.0f;
            __stcs((float2*)(op + HW), o01);

            op += 2 * HW;
        }
    }
}

extern "C" void kernel_launch(void* const* d_in, const int* in_sizes, int n_in,
                              void* d_out, int out_size) {
    const float* l = (const float*)d_in[0];
    const float* r = (const float*)d_in[1];
    float* out = (float*)d_out;

    dim3 grid(H, NN, G);                 // 5120 CTAs: (h, n, group)
    gwc_kernel<<<grid, 160>>>(l, r, out);
}

// round 13
// speedup vs baseline: 1.1459x; 1.1459x over previous
#include <cuda_runtime.h>
#include <cuda_fp16.h>
#include <cstdint>

#define NN 4
#define C  64
#define H  160
#define W  320
#define DISP 48
#define G  8
#define HW (H*W)
#define SMEM_BYTES (W * 16)            // 8 halfs per w position = 16B

// Swizzle for 16B rows: XOR chunk bits [4:7) with bits [7:10).
// Compute lanes step w by 2 and staging lanes step w by 1: both give 8
// distinct 16B chunks per 8-lane phase -> conflict-free (R12-verified).
__device__ __forceinline__ unsigned sw16(int w) {
    unsigned off = (unsigned)w * 16u;
    off ^= (((unsigned)w >> 3) & 7u) << 4;
    return off;
}

// fp16 dot of 8 channels (4 half2 lanes), fp32 finish.
__device__ __forceinline__ float doth(const __half2* l2, const __half2* r2) {
    __half2 a = __hmul2(l2[0], r2[0]);
    a = __hfma2(l2[1], r2[1], a);
    a = __hfma2(l2[2], r2[2], a);
    a = __hfma2(l2[3], r2[3], a);
    float2 f = __half22float2(a);
    return f.x + f.y;
}

__global__ __launch_bounds__(160, 7)
void gwc_kernel(const float* __restrict__ lg,
                const float* __restrict__ rg,
                float* __restrict__ out) {
    __shared__ __align__(16) char rS[SMEM_BYTES];

    const int h   = blockIdx.x;
    const int n   = blockIdx.y;
    const int g   = blockIdx.z;
    const int tid = threadIdx.x;
    const int w0  = tid * 2;             // this thread's 2 output columns

    // ---- l: 8 coalesced LDG.64 (channel pairs), scale 1/8, pack half2 ----
    // lA2[j] = (l[2j], l[2j+1]) at w0 ; lB2[j] = same at w0+1.
    const float* lp = lg + ((n * C + g * 8) * H + h) * W + w0;
    __half2 lA2[4], lB2[4];
    #pragma unroll
    for (int j = 0; j < 4; ++j) {
        float2 v0 = *(const float2*)(lp + (2 * j) * HW);
        float2 v1 = *(const float2*)(lp + (2 * j + 1) * HW);
        lA2[j] = __floats2half2_rn(v0.x * 0.125f, v1.x * 0.125f);
        lB2[j] = __floats2half2_rn(v0.y * 0.125f, v1.y * 0.125f);
    }

    // ---- Stage r channels as fp16, [w][8ch], swizzled ----
    {
        const float* rbase = rg + ((n * C + g * 8) * H + h) * W;
        #pragma unroll
        for (int k = 0; k < 2; ++k) {
            int w = tid + k * 160;
            float f[8];
            #pragma unroll
            for (int c = 0; c < 8; ++c) f[c] = rbase[c * HW + w];
            uint4 hv;
            *(__half2*)&hv.x = __floats2half2_rn(f[0], f[1]);
            *(__half2*)&hv.y = __floats2half2_rn(f[2], f[3]);
            *(__half2*)&hv.z = __floats2half2_rn(f[4], f[5]);
            *(__half2*)&hv.w = __floats2half2_rn(f[6], f[7]);
            *(uint4*)(rS + sw16(w)) = hv;
        }
    }
    __syncthreads();

    // ---- Compute: 2-slot sliding window, all-fp16 ring ----
    __half2 r2[2][4];                    // slot p = parity of r position
    #define LDPOS(wpos, s) do {                                  \
        uint4 _hv = *(const uint4*)(rS + sw16(wpos));            \
        r2[s][0] = *(__half2*)&_hv.x; r2[s][1] = *(__half2*)&_hv.y; \
        r2[s][2] = *(__half2*)&_hv.z; r2[s][3] = *(__half2*)&_hv.w; \
    } while (0)

    LDPOS(w0,     0);
    LDPOS(w0 + 1, 1);

    float* op = out + (((n * G + g) * DISP) * H + h) * W + w0;

    if (w0 >= DISP) {
        #pragma unroll 4
        for (int d2 = 0; d2 < DISP; d2 += 2) {
            // d = d2 (even): output x parity 0, y parity 1
            if (d2 > 0) LDPOS(w0 - d2, 0);
            float2 o01;
            o01.x = doth(lA2, r2[0]);
            o01.y = doth(lB2, r2[1]);
            __stcs((float2*)op, o01);

            // d = d2+1: new position w0-d2-1 has parity 1
            LDPOS(w0 - d2 - 1, 1);
            o01.x = doth(lA2, r2[1]);
            o01.y = doth(lB2, r2[0]);
            __stcs((float2*)(op + HW), o01);

            op += 2 * HW;
        }
    } else {
        #pragma unroll 4
        for (int d2 = 0; d2 < DISP; d2 += 2) {
            const int wn0 = w0 - d2;
            if (d2 > 0 && wn0 >= 0) LDPOS(wn0, 0);
            float2 o01;
            o01.x = (w0     >= d2) ? doth(lA2, r2[0]) : 1.0f;
            o01.y = (w0 + 1 >= d2) ? doth(lB2, r2[1]) : 1.0f;
            __stcs((float2*)op, o01);

            const int wn1 = w0 - d2 - 1;
            if (wn1 >= 0) LDPOS(wn1, 1);
            o01.x = (w0     >= d2 + 1) ? doth(lA2, r2[1]) : 1.0f;
            o01.y = (w0 + 1 >= d2 + 1) ? doth(lB2, r2[0]) : 1.0f;
            __stcs((float2*)(op + HW), o01);

            op += 2 * HW;
        }
    }
    #undef LDPOS
}

extern "C" void kernel_launch(void* const* d_in, const int* in_sizes, int n_in,
                              void* d_out, int out_size) {
    const float* l = (const float*)d_in[0];
    const float* r = (const float*)d_in[1];
    float* out = (float*)d_out;

    dim3 grid(H, NN, G);                 // 5120 CTAs: (h, n, group)
    gwc_kernel<<<grid, 160>>>(l, r, out);
}